// round 11
// baseline (speedup 1.0000x reference)
#include <cuda_runtime.h>

// Problem constants
#define HH 256
#define WW 256
#define CC 64      // content/blur channels, also output channels of deform conv
#define BB 4
#define OC 18      // offset channels actually used (9 o-pairs)
#define HW (HH*WW)

// Deform tiling
#define TS 16                  // pixel tile side
#define HALO 5                 // covers tap(1) + offset(~2.5) + bilinear(1)
#define TDIM (TS + 2*HALO)     // 26
#define TSTRIDE 27             // padded row stride (bank spread)
#define NCP 14                 // weight o-pairs served from constant bank
#define NSP 18                 // weight o-pairs served from shared memory
#define CCHUNK 16              // channels per smem content chunk
#define NCHUNK (CC/CCHUNK)     // 4

typedef unsigned long long ull;

// ---------------------------------------------------------------------------
// f32x2 packed helpers (sm_103a FFMA2 path — only reachable via PTX)
// ---------------------------------------------------------------------------
__device__ __forceinline__ void ffma2(ull& d, ull a, ull b) {
    asm("fma.rn.f32x2 %0, %1, %2, %0;" : "+l"(d) : "l"(a), "l"(b));
}
__device__ __forceinline__ ull packf(float lo, float hi) {
    ull r; asm("mov.b64 %0, {%1, %2};" : "=l"(r) : "f"(lo), "f"(hi)); return r;
}
__device__ __forceinline__ void unpackf(ull v, float& lo, float& hi) {
    asm("mov.b64 {%0, %1}, %2;" : "=f"(lo), "=f"(hi) : "l"(v));
}

// Single constant bank, 64,512 B. Holds offset-conv pairs during kernel A,
// then deform const-side pairs [k][c][j=0..13] during kernel B (stream-ordered
// D2D memcpy-to-symbol nodes between launches).
__constant__ ull c_wbank[9 * CC * NCP];

// Global staging buffers (filled by pack kernels)
__device__ ull g_wcst[9 * CC * NCP];   // deform const-side pairs [k][c][0..13]
__device__ ull g_wsm [9 * CC * NSP];   // deform smem-side pairs  [k][c][14..31]
__device__ ull g_ocst[CC * 9 * 2];     // offset const-side pairs [c*9+k][0..1]
__device__ ull g_osm [CC * 9 * 8];     // offset smem-side pairs  [c*9+k][2..9]

// ---------------------------------------------------------------------------
// Prelude packers
// ---------------------------------------------------------------------------
__global__ void wpack_deform(const float* __restrict__ dw)  // (64,64,3,3)
{
    int idx = blockIdx.x * blockDim.x + threadIdx.x;   // 0 .. 9*64*32-1
    int j = idx & 31;          // o-pair
    int c = (idx >> 5) & 63;
    int k = idx >> 11;
    float w0 = __ldg(dw + ((2 * j)     * CC + c) * 9 + k);
    float w1 = __ldg(dw + ((2 * j + 1) * CC + c) * 9 + k);
    ull v = packf(w0, w1);
    if (j < NCP) g_wcst[(k * CC + c) * NCP + j]         = v;
    else         g_wsm [(k * CC + c) * NSP + (j - NCP)] = v;
}

__global__ void wpack_off(const float* __restrict__ ow)     // (27,64,3,3)
{
    int idx = blockIdx.x * blockDim.x + threadIdx.x;   // 0 .. 64*9*10-1
    if (idx >= CC * 9 * 10) return;
    int j  = idx % 10;               // o-pair 0..9
    int ck = idx / 10;               // c*9 + k
    int o0 = 2 * j, o1 = 2 * j + 1;
    float w0 = (o0 < OC) ? __ldg(ow + o0 * (CC * 9) + ck) : 0.0f;
    float w1 = (o1 < OC) ? __ldg(ow + o1 * (CC * 9) + ck) : 0.0f;
    ull v = packf(w0, w1);
    if (j < 2) g_ocst[ck * 2 + j]       = v;
    else       g_osm [ck * 8 + (j - 2)] = v;
}

// ---------------------------------------------------------------------------
// Kernel A: 3x3 conv (pad 1): blur x offset_w -> offset (18 ch).  (R9 proven)
// Per (c,k): 1 LDC.128 (pairs 0-1) + 4 LDS.128 (pairs 2-9) + 10 FFMA2.
// ---------------------------------------------------------------------------
__global__ __launch_bounds__(256, 4)
void offset_conv_kernel(const float* __restrict__ blur,
                        const float* __restrict__ ob,   // (27,)
                        float* __restrict__ off_out)    // (4,18,256,256)
{
    __shared__ ull s_ow[CC * 9 * 8];   // 36,864 B

    const int tid = threadIdx.x;
    {   // stage smem-side weights once (coalesced 16B copies)
        const ulonglong2* src = reinterpret_cast<const ulonglong2*>(g_osm);
        ulonglong2* dst = reinterpret_cast<ulonglong2*>(s_ow);
        for (int i = tid; i < CC * 9 * 4; i += blockDim.x)
            dst[i] = __ldg(src + i);
    }
    __syncthreads();

    const int p = blockIdx.x * blockDim.x + tid;
    const int x = p & (WW - 1);
    const int y = (p >> 8) & (HH - 1);
    const int b = p >> 16;

    ull acc[10];
#pragma unroll
    for (int j = 0; j < 10; j++) acc[j] = 0ull;

    const float* bp = blur + (size_t)b * CC * HW;
    const ulonglong2* cb2 = reinterpret_cast<const ulonglong2*>(c_wbank);
    const ulonglong2* sw2 = reinterpret_cast<const ulonglong2*>(s_ow);

    for (int c = 0; c < CC; c++) {
        const float* cp = bp + c * HW;
#pragma unroll
        for (int k = 0; k < 9; k++) {
            const int iy = y + k / 3 - 1;
            const int ix = x + k % 3 - 1;
            float v = 0.0f;
            if (iy >= 0 && iy < HH && ix >= 0 && ix < WW)
                v = __ldg(cp + iy * WW + ix);
            const ull vv = packf(v, v);
            const int ck = c * 9 + k;

            ulonglong2 wc = cb2[ck];             // pairs 0,1 (constant port)
            ffma2(acc[0], wc.x, vv);
            ffma2(acc[1], wc.y, vv);

            const ulonglong2* ws = sw2 + ck * 4; // pairs 2..9 (smem)
#pragma unroll
            for (int t = 0; t < 4; t++) {
                ulonglong2 w = ws[t];
                ffma2(acc[2 + 2 * t], w.x, vv);
                ffma2(acc[3 + 2 * t], w.y, vv);
            }
        }
    }

    float* op = off_out + ((size_t)b * OC) * HW + y * WW + x;
#pragma unroll
    for (int j = 0; j < OC / 2; j++) {   // pairs 0..8 cover o = 0..17
        float a0, a1;
        unpackf(acc[j], a0, a1);
        op[(2 * j)     * HW] = a0 + __ldg(ob + 2 * j);
        op[(2 * j + 1) * HW] = a1 + __ldg(ob + 2 * j + 1);
    }
}

// ---------------------------------------------------------------------------
// 32-pair MAC: 7 LDC.128 (const pairs 0..13) + 9 LDS.128 (smem pairs 14..31)
// ---------------------------------------------------------------------------
__device__ __forceinline__ void mac32(ull* acc, ull vv,
                                      const ulonglong2* __restrict__ wc,
                                      const ulonglong2* __restrict__ ws)
{
#pragma unroll
    for (int t = 0; t < 7; t++) {
        ulonglong2 w = wc[t];
        ffma2(acc[2 * t],     w.x, vv);
        ffma2(acc[2 * t + 1], w.y, vv);
    }
#pragma unroll
    for (int t = 0; t < 9; t++) {
        ulonglong2 w = ws[t];
        ffma2(acc[14 + 2 * t], w.x, vv);
        ffma2(acc[15 + 2 * t], w.y, vv);
    }
}

// ---------------------------------------------------------------------------
// Kernel B: deformable conv, ALL 9 taps, one launch.
// Block = 16x16 pixel tile. Per 16-channel chunk: stage a 26x26 content
// window to smem (bilinear gathers become near-conflict-free LDS instead of
// row-divergent LDG) + that chunk's smem-side weights. Rare out-of-window
// samples fall back to global gathers (exact same math).
// ---------------------------------------------------------------------------
__global__ __launch_bounds__(256, 2)
void deform_kernel(const float* __restrict__ content,
                   const float* __restrict__ offset,  // (4,18,256,256)
                   const float* __restrict__ db,      // (64,)
                   float* __restrict__ out)           // (4,64,256,256)
{
    extern __shared__ char smem_raw[];
    float* s_t = reinterpret_cast<float*>(smem_raw);                 // [16][26][27] = 44,928 B
    ull*   s_w = reinterpret_cast<ull*>(smem_raw + CCHUNK * TDIM * TSTRIDE * 4); // [9][16][18] = 20,736 B

    const int tid = threadIdx.x;
    const int blk = blockIdx.x;
    const int tx = blk & 15;
    const int ty = (blk >> 4) & 15;
    const int b  = blk >> 8;

    const int lx  = tid & 15;
    const int lyr = tid >> 4;
    const int x = tx * TS + lx;
    const int y = ty * TS + lyr;
    const int gy0 = ty * TS - HALO;
    const int gx0 = tx * TS - HALO;

    ull acc[32];
#pragma unroll
    for (int j = 0; j < 32; j++) acc[j] = 0ull;

    const float* cb   = content + (size_t)b * CC * HW;
    const float* offb = offset + (size_t)b * OC * HW + y * WW + x;

    for (int chunk = 0; chunk < NCHUNK; chunk++) {
        const int c0 = chunk * CCHUNK;
        __syncthreads();

        // ---- stage 26x26 content window for 16 channels (border-clamped) ----
        for (int i = tid; i < CCHUNK * TDIM * TDIM; i += 256) {
            int cc  = i / (TDIM * TDIM);
            int r   = (i / TDIM) % TDIM;
            int col = i % TDIM;
            int gy = min(max(gy0 + r,   0), HH - 1);
            int gx = min(max(gx0 + col, 0), WW - 1);
            s_t[cc * (TDIM * TSTRIDE) + r * TSTRIDE + col] =
                __ldg(cb + (c0 + cc) * HW + gy * WW + gx);
        }
        // ---- stage this chunk's smem-side weights [k][cc][18] ----
        for (int i = tid; i < 9 * CCHUNK * NSP; i += 256) {
            int k   = i / (CCHUNK * NSP);
            int rem = i % (CCHUNK * NSP);
            int cc  = rem / NSP;
            int j   = rem % NSP;
            s_w[i] = __ldg(g_wsm + ((size_t)k * CC + c0 + cc) * NSP + j);
        }
        __syncthreads();

#pragma unroll
        for (int k = 0; k < 9; k++) {
            const float offy = __ldg(offb + (2 * k) * HW);
            const float offx = __ldg(offb + (2 * k + 1) * HW);
            const float py = (float)(y + (k / 3) - 1) + offy;
            const float px = (float)(x + (k % 3) - 1) + offx;

            const float y0f = floorf(py);
            const float x0f = floorf(px);
            const float wy = py - y0f;
            const float wx = px - x0f;
            const int iy0 = (int)y0f, ix0 = (int)x0f;
            const int iy1 = iy0 + 1,  ix1 = ix0 + 1;

            const bool vy0 = (iy0 >= 0) && (iy0 < HH);
            const bool vy1 = (iy1 >= 0) && (iy1 < HH);
            const bool vx0 = (ix0 >= 0) && (ix0 < WW);
            const bool vx1 = (ix1 >= 0) && (ix1 < WW);

            const float w00 = (1.f - wy) * (1.f - wx) * ((vy0 && vx0) ? 1.f : 0.f);
            const float w01 = (1.f - wy) * wx         * ((vy0 && vx1) ? 1.f : 0.f);
            const float w10 = wy * (1.f - wx)         * ((vy1 && vx0) ? 1.f : 0.f);
            const float w11 = wy * wx                 * ((vy1 && vx1) ? 1.f : 0.f);

            const int cy0 = min(max(iy0, 0), HH - 1);
            const int cy1 = min(max(iy1, 0), HH - 1);
            const int cx0 = min(max(ix0, 0), WW - 1);
            const int cx1 = min(max(ix1, 0), WW - 1);

            const int ly0 = cy0 - gy0, ly1 = cy1 - gy0;
            const int lx0 = cx0 - gx0, lx1 = cx1 - gx0;
            const bool in_tile = (ly0 >= 0) && (ly1 <= TDIM - 1) &&
                                 (lx0 >= 0) && (lx1 <= TDIM - 1);

            const ulonglong2* cbank = reinterpret_cast<const ulonglong2*>(c_wbank)
                                    + ((size_t)k * CC + c0) * (NCP / 2);
            const ulonglong2* sbank = reinterpret_cast<const ulonglong2*>(
                                          s_w + k * CCHUNK * NSP);

            if (in_tile) {
                const int o00 = ly0 * TSTRIDE + lx0;
                const int o01 = ly0 * TSTRIDE + lx1;
                const int o10 = ly1 * TSTRIDE + lx0;
                const int o11 = ly1 * TSTRIDE + lx1;
#pragma unroll 2
                for (int cc = 0; cc < CCHUNK; cc++) {
                    const float* st = s_t + cc * (TDIM * TSTRIDE);
                    const float samp = w00 * st[o00] + w01 * st[o01]
                                     + w10 * st[o10] + w11 * st[o11];
                    mac32(acc, packf(samp, samp),
                          cbank + cc * (NCP / 2), sbank + cc * (NSP / 2));
                }
            } else {
                const int i00 = cy0 * WW + cx0;
                const int i01 = cy0 * WW + cx1;
                const int i10 = cy1 * WW + cx0;
                const int i11 = cy1 * WW + cx1;
#pragma unroll 2
                for (int cc = 0; cc < CCHUNK; cc++) {
                    const float* cp = cb + (c0 + cc) * HW;
                    const float samp = w00 * __ldg(cp + i00) + w01 * __ldg(cp + i01)
                                     + w10 * __ldg(cp + i10) + w11 * __ldg(cp + i11);
                    mac32(acc, packf(samp, samp),
                          cbank + cc * (NCP / 2), sbank + cc * (NSP / 2));
                }
            }
        }
    }

    // epilogue: unpack 32 o-pairs -> 64 channels (+bias)
    float* op = out + (size_t)b * CC * HW + y * WW + x;
#pragma unroll
    for (int j = 0; j < 32; j++) {
        float a0, a1;
        unpackf(acc[j], a0, a1);
        op[(2 * j)     * HW] = a0 + __ldg(db + 2 * j);
        op[(2 * j + 1) * HW] = a1 + __ldg(db + 2 * j + 1);
    }
}

// ---------------------------------------------------------------------------
// kernel_launch
//   d_in[0] content_feats (4,64,256,256) f32
//   d_in[1] blur_feats    (4,64,256,256) f32
//   d_in[2] offset_w      (27,64,3,3)    f32
//   d_in[3] offset_b      (27,)          f32
//   d_in[4] dc_w          (64,64,3,3)    f32
//   d_in[5] dc_b          (64,)          f32
// d_out = [ out (4,64,256,256) | offset (4,18,256,256) ]
// ---------------------------------------------------------------------------
extern "C" void kernel_launch(void* const* d_in, const int* in_sizes, int n_in,
                              void* d_out, int out_size)
{
    const float* content = (const float*)d_in[0];
    const float* blur    = (const float*)d_in[1];
    const float* ow      = (const float*)d_in[2];
    const float* ob      = (const float*)d_in[3];
    const float* dw      = (const float*)d_in[4];
    const float* db      = (const float*)d_in[5];

    float* out     = (float*)d_out;
    float* off_out = out + (size_t)BB * CC * HW;

    void* wcst_addr = nullptr;
    void* ocst_addr = nullptr;
    cudaGetSymbolAddress(&wcst_addr, g_wcst);
    cudaGetSymbolAddress(&ocst_addr, g_ocst);

    const int smem_deform = CCHUNK * TDIM * TSTRIDE * 4 + 9 * CCHUNK * NSP * 8; // 65,664
    cudaFuncSetAttribute(deform_kernel,
                         cudaFuncAttributeMaxDynamicSharedMemorySize, smem_deform);

    // 1) pack weights into split pair layouts
    wpack_deform<<<(9 * CC * 32) / 256, 256>>>(dw);
    wpack_off<<<(CC * 9 * 10 + 255) / 256, 256>>>(ow);

    // 2) offset conv (const bank <- offset-conv const-side pairs)
    cudaMemcpyToSymbolAsync(c_wbank, ocst_addr,
                            (size_t)CC * 9 * 2 * sizeof(ull), 0,
                            cudaMemcpyDeviceToDevice, 0);
    offset_conv_kernel<<<(BB * HW) / 256, 256>>>(blur, ob, off_out);

    // 3) deform conv, all 9 taps, one launch (const bank <- deform pairs)
    cudaMemcpyToSymbolAsync(c_wbank, wcst_addr,
                            (size_t)9 * CC * NCP * sizeof(ull), 0,
                            cudaMemcpyDeviceToDevice, 0);
    deform_kernel<<<BB * TS * TS, 256, smem_deform>>>(content, off_out, db, out);
}

// round 13
// speedup vs baseline: 1.2617x; 1.2617x over previous
#include <cuda_runtime.h>

// Problem constants
#define HH 256
#define WW 256
#define CC 64      // content/blur channels, also output channels of deform conv
#define BB 4
#define OC 18      // offset channels actually used (9 o-pairs)
#define HW (HH*WW)

typedef unsigned long long ull;

// ---------------------------------------------------------------------------
// f32x2 packed helpers (sm_103a FFMA2 path — only reachable via PTX)
// ---------------------------------------------------------------------------
__device__ __forceinline__ void ffma2(ull& d, ull a, ull b) {
    asm("fma.rn.f32x2 %0, %1, %2, %0;" : "+l"(d) : "l"(a), "l"(b));
}
__device__ __forceinline__ ull packf(float lo, float hi) {
    ull r; asm("mov.b64 %0, {%1, %2};" : "=l"(r) : "f"(lo), "f"(hi)); return r;
}
__device__ __forceinline__ void unpackf(ull v, float& lo, float& hi) {
    asm("mov.b64 {%0, %1}, %2;" : "=f"(lo), "=f"(hi) : "l"(v));
}

// Single constant bank (41,472 B), reloaded between launches via async D2D
// memcpy-to-symbol nodes. Kernel A: all 9 offset-conv o-pairs per (c,k).
// Kernel B: deform const-side pairs [kk][c][0..9] for the current 3-tap group.
__constant__ ull c_wbank[CC * 9 * 9];

// Global staging buffers (filled by pack kernels)
__device__ ull g_wcst [9 * CC * 10];   // deform const-side pairs [k][c][0..9]
__device__ ull g_wsm  [9 * CC * 22];   // deform smem-side pairs  [k][c][10..31]
__device__ ull g_ocst9[CC * 9 * 9];    // offset pairs [c*9+k][0..8] (all const)

// ---------------------------------------------------------------------------
// Prelude packers
// ---------------------------------------------------------------------------
__global__ void wpack_deform(const float* __restrict__ dw)  // (64,64,3,3)
{
    int idx = blockIdx.x * blockDim.x + threadIdx.x;   // 0 .. 9*64*32-1
    int j = idx & 31;          // o-pair
    int c = (idx >> 5) & 63;
    int k = idx >> 11;
    float w0 = __ldg(dw + ((2 * j)     * CC + c) * 9 + k);
    float w1 = __ldg(dw + ((2 * j + 1) * CC + c) * 9 + k);
    ull v = packf(w0, w1);
    if (j < 10) g_wcst[(k * CC + c) * 10 + j]        = v;
    else        g_wsm [(k * CC + c) * 22 + (j - 10)] = v;
}

__global__ void wpack_off(const float* __restrict__ ow)     // (27,64,3,3)
{
    int idx = blockIdx.x * blockDim.x + threadIdx.x;   // 0 .. 64*9*9-1
    if (idx >= CC * 9 * 9) return;
    int j  = idx % 9;                // o-pair 0..8
    int ck = idx / 9;                // c*9 + k
    float w0 = __ldg(ow + (2 * j)     * (CC * 9) + ck);
    float w1 = __ldg(ow + (2 * j + 1) * (CC * 9) + ck);
    g_ocst9[idx] = packf(w0, w1);
}

// ---------------------------------------------------------------------------
// Kernel A: 3x3 conv (pad 1): blur x offset_w -> offset (18 ch).
// R8-proven pure-constant version: 9 o-pair accumulators, weights entirely
// from the constant bank (uniform port), no smem, no barriers.
// ---------------------------------------------------------------------------
__global__ __launch_bounds__(256, 4)
void offset_conv_kernel(const float* __restrict__ blur,
                        const float* __restrict__ ob,   // (27,)
                        float* __restrict__ off_out)    // (4,18,256,256)
{
    const int tid = threadIdx.x;
    const int p = blockIdx.x * blockDim.x + tid;
    const int x = p & (WW - 1);
    const int y = (p >> 8) & (HH - 1);
    const int b = p >> 16;

    ull acc[9];
#pragma unroll
    for (int j = 0; j < 9; j++) acc[j] = 0ull;

    const float* bp = blur + (size_t)b * CC * HW;

    for (int c = 0; c < CC; c++) {
        const float* cp = bp + c * HW;
#pragma unroll
        for (int k = 0; k < 9; k++) {
            const int iy = y + k / 3 - 1;
            const int ix = x + k % 3 - 1;
            float v = 0.0f;
            if (iy >= 0 && iy < HH && ix >= 0 && ix < WW)
                v = __ldg(cp + iy * WW + ix);
            const ull vv = packf(v, v);
            const ull* wp = c_wbank + (c * 9 + k) * 9;
#pragma unroll
            for (int j = 0; j < 9; j++)
                ffma2(acc[j], wp[j], vv);
        }
    }

    float* op = off_out + ((size_t)b * OC) * HW + y * WW + x;
#pragma unroll
    for (int j = 0; j < 9; j++) {
        float a0, a1;
        unpackf(acc[j], a0, a1);
        op[(2 * j)     * HW] = a0 + __ldg(ob + 2 * j);
        op[(2 * j + 1) * HW] = a1 + __ldg(ob + 2 * j + 1);
    }
}

// ---------------------------------------------------------------------------
// 32-pair MAC: 5 LDC.128 (const pairs 0..9) + 11 LDS.128 (smem pairs 10..31)
// ---------------------------------------------------------------------------
__device__ __forceinline__ void mac32(ull* acc, ull vv,
                                      const ulonglong2* __restrict__ wc,
                                      const ulonglong2* __restrict__ ws)
{
#pragma unroll
    for (int t = 0; t < 5; t++) {
        ulonglong2 w = wc[t];
        ffma2(acc[2 * t],     w.x, vv);
        ffma2(acc[2 * t + 1], w.y, vv);
    }
#pragma unroll
    for (int t = 0; t < 11; t++) {
        ulonglong2 w = ws[t];
        ffma2(acc[10 + 2 * t], w.x, vv);
        ffma2(acc[11 + 2 * t], w.y, vv);
    }
}

// ---------------------------------------------------------------------------
// Kernel B: deformable conv, 3 taps per launch (R9-proven structure) with
// depth-1 software pipelining of the bilinear corner gathers: the 4 corner
// LDGs for channel c+1 are issued before the MAC of channel c, doubling
// per-warp memory-level parallelism to hide L2 latency (occ is reg-capped
// at 16 warps/SM, so latency must be hidden within each warp).
// ---------------------------------------------------------------------------
__global__ __launch_bounds__(256, 2)
void deform_group_kernel(const float* __restrict__ content,
                         const float* __restrict__ offset,  // (4,18,256,256)
                         const float* __restrict__ db,      // (64,)
                         float* __restrict__ out,           // (4,64,256,256)
                         int k0, int first)
{
    __shared__ ull s_w[3 * CC * 22];   // 33,792 B

    const int tid = threadIdx.x;
    {   // stage smem-side weights for this tap group (coalesced)
        const ulonglong2* src = reinterpret_cast<const ulonglong2*>(
            g_wsm + (size_t)k0 * CC * 22);
        ulonglong2* dst = reinterpret_cast<ulonglong2*>(s_w);
        for (int i = tid; i < 3 * CC * 11; i += blockDim.x)
            dst[i] = __ldg(src + i);
    }
    __syncthreads();

    const int p = blockIdx.x * blockDim.x + tid;
    const int x = p & (WW - 1);
    const int y = (p >> 8) & (HH - 1);
    const int b = p >> 16;

    ull acc[32];                   // o-pair accumulators (64 channels)
#pragma unroll
    for (int j = 0; j < 32; j++) acc[j] = 0ull;

    const float* cb   = content + (size_t)b * CC * HW;
    const float* offb = offset + (size_t)b * OC * HW + y * WW + x;

#pragma unroll
    for (int kk = 0; kk < 3; kk++) {
        const int k = k0 + kk;

        const float offy = __ldg(offb + (2 * k) * HW);
        const float offx = __ldg(offb + (2 * k + 1) * HW);
        const float py = (float)(y + (k / 3) - 1) + offy;
        const float px = (float)(x + (k % 3) - 1) + offx;

        const float y0f = floorf(py);
        const float x0f = floorf(px);
        const float wy = py - y0f;
        const float wx = px - x0f;
        const int iy0 = (int)y0f, ix0 = (int)x0f;
        const int iy1 = iy0 + 1,  ix1 = ix0 + 1;

        const bool vy0 = (iy0 >= 0) && (iy0 < HH);
        const bool vy1 = (iy1 >= 0) && (iy1 < HH);
        const bool vx0 = (ix0 >= 0) && (ix0 < WW);
        const bool vx1 = (ix1 >= 0) && (ix1 < WW);

        const float w00 = (1.f - wy) * (1.f - wx) * ((vy0 && vx0) ? 1.f : 0.f);
        const float w01 = (1.f - wy) * wx         * ((vy0 && vx1) ? 1.f : 0.f);
        const float w10 = wy * (1.f - wx)         * ((vy1 && vx0) ? 1.f : 0.f);
        const float w11 = wy * wx                 * ((vy1 && vx1) ? 1.f : 0.f);

        const int cy0 = min(max(iy0, 0), HH - 1);
        const int cy1 = min(max(iy1, 0), HH - 1);
        const int cx0 = min(max(ix0, 0), WW - 1);
        const int cx1 = min(max(ix1, 0), WW - 1);

        const float* p00 = cb + cy0 * WW + cx0;
        const float* p01 = cb + cy0 * WW + cx1;
        const float* p10 = cb + cy1 * WW + cx0;
        const float* p11 = cb + cy1 * WW + cx1;

        const ulonglong2* cbank = reinterpret_cast<const ulonglong2*>(c_wbank)
                                + kk * (CC * 5);
        const ulonglong2* sbank = reinterpret_cast<const ulonglong2*>(s_w)
                                + kk * (CC * 11);

        // ---- software-pipelined gather + MAC over channels ----
        float a00 = __ldg(p00), a01 = __ldg(p01);
        float a10 = __ldg(p10), a11 = __ldg(p11);

#pragma unroll 2
        for (int c = 0; c < CC; c++) {
            // prefetch channel c+1 (clamped; final extra load is an L1 hit)
            const int nco = (c + 1 < CC ? c + 1 : c) * HW;
            const float n00 = __ldg(p00 + nco);
            const float n01 = __ldg(p01 + nco);
            const float n10 = __ldg(p10 + nco);
            const float n11 = __ldg(p11 + nco);

            const float samp = w00 * a00 + w01 * a01 + w10 * a10 + w11 * a11;
            mac32(acc, packf(samp, samp), cbank + c * 5, sbank + c * 11);

            a00 = n00; a01 = n01; a10 = n10; a11 = n11;
        }
    }

    // epilogue: unpack 32 o-pairs -> 64 channels, coalesced
    float* op = out + (size_t)b * CC * HW + y * WW + x;
    if (first) {
#pragma unroll
        for (int j = 0; j < 32; j++) {
            float a0, a1;
            unpackf(acc[j], a0, a1);
            op[(2 * j)     * HW] = a0 + __ldg(db + 2 * j);
            op[(2 * j + 1) * HW] = a1 + __ldg(db + 2 * j + 1);
        }
    } else {
#pragma unroll
        for (int j = 0; j < 32; j++) {
            float a0, a1;
            unpackf(acc[j], a0, a1);
            op[(2 * j)     * HW] += a0;
            op[(2 * j + 1) * HW] += a1;
        }
    }
}

// ---------------------------------------------------------------------------
// kernel_launch
//   d_in[0] content_feats (4,64,256,256) f32
//   d_in[1] blur_feats    (4,64,256,256) f32
//   d_in[2] offset_w      (27,64,3,3)    f32
//   d_in[3] offset_b      (27,)          f32
//   d_in[4] dc_w          (64,64,3,3)    f32
//   d_in[5] dc_b          (64,)          f32
// d_out = [ out (4,64,256,256) | offset (4,18,256,256) ]
// ---------------------------------------------------------------------------
extern "C" void kernel_launch(void* const* d_in, const int* in_sizes, int n_in,
                              void* d_out, int out_size)
{
    const float* content = (const float*)d_in[0];
    const float* blur    = (const float*)d_in[1];
    const float* ow      = (const float*)d_in[2];
    const float* ob      = (const float*)d_in[3];
    const float* dw      = (const float*)d_in[4];
    const float* db      = (const float*)d_in[5];

    float* out     = (float*)d_out;
    float* off_out = out + (size_t)BB * CC * HW;

    void* wcst_addr = nullptr;
    void* ocst_addr = nullptr;
    cudaGetSymbolAddress(&wcst_addr, g_wcst);
    cudaGetSymbolAddress(&ocst_addr, g_ocst9);
    const ull* wcst_p = (const ull*)wcst_addr;

    // 1) pack weights into pair layouts
    wpack_deform<<<(9 * CC * 32) / 256, 256>>>(dw);
    wpack_off<<<(CC * 9 * 9 + 255) / 256, 256>>>(ow);

    // 2) offset conv (const bank <- all 9 offset o-pairs)
    cudaMemcpyToSymbolAsync(c_wbank, ocst_addr,
                            (size_t)CC * 9 * 9 * sizeof(ull), 0,
                            cudaMemcpyDeviceToDevice, 0);
    offset_conv_kernel<<<(BB * HW) / 256, 256>>>(blur, ob, off_out);

    // 3) deform conv in 3 tap-groups; const bank reloaded per group
    const size_t grp_bytes = (size_t)3 * CC * 10 * sizeof(ull);   // 15,360
    for (int g = 0; g < 3; g++) {
        cudaMemcpyToSymbolAsync(c_wbank, wcst_p + (size_t)g * 3 * CC * 10,
                                grp_bytes, 0, cudaMemcpyDeviceToDevice, 0);
        deform_group_kernel<<<(BB * HW) / 256, 256>>>(
            content, off_out, db, out, 3 * g, g == 0 ? 1 : 0);
    }
}